// round 5
// baseline (speedup 1.0000x reference)
#include <cuda_runtime.h>
#include <cuda_bf16.h>
#include <cstdint>

#define DINLINE __device__ __forceinline__

// ---------------------------------------------------------------------------
// Problem constants
// ---------------------------------------------------------------------------
constexpr int NTOK  = 8192;   // B*S tokens
constexpr int IN    = 4096;
constexpr int OUT   = 4096;
constexpr int POOLS = 128;
constexpr int SEGS  = 3;      // bf16 split: xh*wh + xh*wl + xl*wh

constexpr int BM      = 128;
constexpr int BN      = 128;
constexpr int BK      = 64;   // bf16 per k-chunk -> 128B rows
constexpr int STAGES  = 4;
constexpr int THREADS = 256;  // 8 warps: 2 (m) x 4 (n), warp tile 64x32

constexpr int CHUNKS_PER_SEG = IN / BK;               // 64
constexpr int NC             = SEGS * CHUNKS_PER_SEG; // 192

constexpr int A_BYTES     = BM * 128;                 // 16 KB
constexpr int B_BYTES     = BN * 128;                 // 16 KB
constexpr int STAGE_BYTES = A_BYTES + B_BYTES;        // 32 KB
constexpr int SMEM_TOTAL  = STAGES * STAGE_BYTES;     // 128 KB

// ---------------------------------------------------------------------------
// Device scratch (static __device__ globals only — no runtime allocation)
// ---------------------------------------------------------------------------
__device__ __align__(1024) __nv_bfloat16 g_xhi [(size_t)NTOK * IN];
__device__ __align__(1024) __nv_bfloat16 g_xlo [(size_t)NTOK * IN];
__device__ __align__(1024) __nv_bfloat16 g_whi [(size_t)OUT * IN];
__device__ __align__(1024) __nv_bfloat16 g_wlo [(size_t)OUT * IN];
__device__ __align__(1024) __nv_bfloat16 g_wrhi[(size_t)POOLS * IN];
__device__ __align__(1024) __nv_bfloat16 g_wrlo[(size_t)POOLS * IN];
__device__ __align__(1024) float g_logits[(size_t)NTOK * POOLS];
__device__ float g_dotv[(size_t)NTOK * 2];
__device__ int   g_idxv[(size_t)NTOK * 2];

// ---------------------------------------------------------------------------
// Portable PTX helpers (all valid on plain sm_103 target)
// ---------------------------------------------------------------------------
DINLINE uint32_t smem_u32(const void* p) {
    uint32_t a;
    asm("{ .reg .u64 t; cvta.to.shared.u64 t, %1; cvt.u32.u64 %0, t; }" : "=r"(a) : "l"(p));
    return a;
}

// 128B-row swizzle: 16B-chunk index (bits 4..6) ^= low 3 bits of row (bits 7..9)
#define SWZ128(o) ((o) ^ (((o) >> 3) & 0x70))

#define CP_ASYNC16(saddr, gptr) \
    asm volatile("cp.async.cg.shared.global [%0], [%1], 16;" :: "r"(saddr), "l"(gptr))
#define CP_COMMIT() asm volatile("cp.async.commit_group;" ::: "memory")
#define CP_WAIT2()  asm volatile("cp.async.wait_group 2;"  ::: "memory")

DINLINE void ldsm_x4(uint32_t* r, uint32_t addr) {
    asm volatile("ldmatrix.sync.aligned.m8n8.x4.shared.b16 {%0,%1,%2,%3}, [%4];"
                 : "=r"(r[0]), "=r"(r[1]), "=r"(r[2]), "=r"(r[3]) : "r"(addr));
}

DINLINE void mma16816(float* d, const uint32_t* a, uint32_t b0, uint32_t b1) {
    asm volatile(
        "mma.sync.aligned.m16n8k16.row.col.f32.bf16.bf16.f32 "
        "{%0,%1,%2,%3}, {%4,%5,%6,%7}, {%8,%9}, {%0,%1,%2,%3};"
        : "+f"(d[0]), "+f"(d[1]), "+f"(d[2]), "+f"(d[3])
        : "r"(a[0]), "r"(a[1]), "r"(a[2]), "r"(a[3]), "r"(b0), "r"(b1));
}

// ---------------------------------------------------------------------------
// Kernel 0: fp32 -> (bf16 hi, bf16 lo) split
// ---------------------------------------------------------------------------
__global__ void split_kernel(const float* __restrict__ src, int which, int n) {
    __nv_bfloat16* hi = (which == 0) ? g_xhi : (which == 1) ? g_whi : g_wrhi;
    __nv_bfloat16* lo = (which == 0) ? g_xlo : (which == 1) ? g_wlo : g_wrlo;
    int i = blockIdx.x * blockDim.x + threadIdx.x;
    int stride = gridDim.x * blockDim.x;
    for (; i < n; i += stride) {
        float v = src[i];
        __nv_bfloat16 h = __float2bfloat16(v);
        hi[i] = h;
        lo[i] = __float2bfloat16(v - __bfloat162float(h));
    }
}

// ---------------------------------------------------------------------------
// GEMM: out = x @ W^T with split-bf16 (fp32-equivalent accuracy).
//   MAIN=false: logits[8192,128] = x @ wr^T
//   MAIN=true : out[8192,4096]  = x @ w0^T + b0 + rank-one expert epilogue
// cp.async 4-stage pipeline, ldmatrix + mma.sync.m16n8k16 (portable HMMA).
// ---------------------------------------------------------------------------
template <bool MAIN>
__global__ void __launch_bounds__(THREADS, 1)
gemm_kernel(const float* __restrict__ b0v, const float* __restrict__ u,
            float* __restrict__ out) {
    extern __shared__ __align__(1024) char smem[];
    const uint32_t smem_base = smem_u32(smem);

    const int tid    = threadIdx.x;
    const int wid    = tid >> 5;
    const int lane   = tid & 31;
    const int warp_m = wid & 1;   // 0..1
    const int warp_n = wid >> 1;  // 0..3

    // group-swizzled CTA rasterization (keeps ~16 A-tiles + ~10 B-tiles in L2)
    const int num_n = MAIN ? (OUT / BN) : 1;
    constexpr int GM = 16;
    const int per_group = GM * (MAIN ? (OUT / BN) : 1);
    const int id = blockIdx.x;
    const int m_tile = (id / per_group) * GM + (id % per_group) % GM;
    const int n_tile = ((id % per_group) / GM);
    const int m0 = m_tile * BM;
    const int n0 = n_tile * BN;
    (void)num_n;

    const __nv_bfloat16* Aseg[SEGS] = {g_xhi, g_xhi, g_xlo};
    const __nv_bfloat16* Bseg[SEGS];
    if (MAIN) { Bseg[0] = g_whi;  Bseg[1] = g_wlo;  Bseg[2] = g_whi;  }
    else      { Bseg[0] = g_wrhi; Bseg[1] = g_wrlo; Bseg[2] = g_wrhi; }

    auto load_chunk = [&](int chunk, int stage) {
        const int seg = chunk >> 6;          // / CHUNKS_PER_SEG
        const int kc  = chunk & 63;
        const __nv_bfloat16* Ap = Aseg[seg] + (size_t)m0 * IN + kc * BK;
        const __nv_bfloat16* Bp = Bseg[seg] + (size_t)n0 * IN + kc * BK;
        const uint32_t sA = smem_base + stage * STAGE_BYTES;
        const uint32_t sB = sA + A_BYTES;
#pragma unroll
        for (int it = 0; it < 4; it++) {     // 1024 x 16B for A, 4 per thread
            int s = tid + it * THREADS;
            int row = s >> 3, c = s & 7;
            CP_ASYNC16(sA + SWZ128((uint32_t)(row * 128 + c * 16)),
                       (const void*)(Ap + (size_t)row * IN + c * 8));
        }
#pragma unroll
        for (int it = 0; it < 4; it++) {
            int s = tid + it * THREADS;
            int row = s >> 3, c = s & 7;
            CP_ASYNC16(sB + SWZ128((uint32_t)(row * 128 + c * 16)),
                       (const void*)(Bp + (size_t)row * IN + c * 8));
        }
    };

    // Per-thread ldmatrix row bases.
    // A (m16x16 tiles): row = warp_m*64 + mt*16 + (lane&15), chunk = ks*2 + (lane>>4)
    // B (n16x16 tiles): row = warp_n*32 + nt2*16 + ((lane&7) | ((lane&16)>>1)),
    //                   chunk = ks*2 + ((lane>>3)&1)
    const int xorv   = lane & 7;             // low-3 row bits for both A and B
    const int a_hi   = lane >> 4;            // A k-chunk select
    const int b_hi   = (lane >> 3) & 1;      // B k-chunk select
    uint32_t a_row[4], b_row[2];
#pragma unroll
    for (int mt = 0; mt < 4; mt++)
        a_row[mt] = (uint32_t)((warp_m * 64 + mt * 16 + (lane & 15)) * 128);
#pragma unroll
    for (int nt2 = 0; nt2 < 2; nt2++)
        b_row[nt2] = (uint32_t)(A_BYTES +
                     (warp_n * 32 + nt2 * 16 + ((lane & 7) | ((lane & 16) >> 1))) * 128);

    float acc[4][4][4] = {};

    // prologue: stages 0..STAGES-2
#pragma unroll
    for (int s = 0; s < STAGES - 1; s++) { load_chunk(s, s); CP_COMMIT(); }

    for (int i = 0; i < NC; i++) {
        const int pre = i + STAGES - 1;
        if (pre < NC) load_chunk(pre, pre & (STAGES - 1));
        CP_COMMIT();
        CP_WAIT2();
        __syncthreads();

        const uint32_t sbase = smem_base + (i & (STAGES - 1)) * STAGE_BYTES;
#pragma unroll
        for (int ks = 0; ks < 4; ks++) {
            uint32_t af[4][4], bf[2][4];
#pragma unroll
            for (int mt = 0; mt < 4; mt++) {
                uint32_t chunk = (uint32_t)((ks * 2 + a_hi) ^ xorv) << 4;
                ldsm_x4(af[mt], sbase + a_row[mt] + chunk);
            }
#pragma unroll
            for (int nt2 = 0; nt2 < 2; nt2++) {
                uint32_t chunk = (uint32_t)((ks * 2 + b_hi) ^ xorv) << 4;
                ldsm_x4(bf[nt2], sbase + b_row[nt2] + chunk);
            }
#pragma unroll
            for (int mt = 0; mt < 4; mt++)
#pragma unroll
                for (int nt2 = 0; nt2 < 2; nt2++) {
                    mma16816(acc[mt][nt2 * 2 + 0], af[mt], bf[nt2][0], bf[nt2][1]);
                    mma16816(acc[mt][nt2 * 2 + 1], af[mt], bf[nt2][2], bf[nt2][3]);
                }
        }
        __syncthreads();
    }

    // ---------------- epilogue (C frag: rows l>>2 and +8, cols (l&3)*2+{0,1}) --
    const int qrow = lane >> 2;
    const int qcol = (lane & 3) * 2;

    if (MAIN) {
        float bo[4][2];
#pragma unroll
        for (int nt = 0; nt < 4; nt++) {
            int o = n0 + warp_n * 32 + nt * 8 + qcol;
            bo[nt][0] = b0v[o];
            bo[nt][1] = b0v[o + 1];
        }
#pragma unroll
        for (int mt = 0; mt < 4; mt++)
#pragma unroll
            for (int g = 0; g < 2; g++) {
                const int ntok = m0 + warp_m * 64 + mt * 16 + g * 8 + qrow;
                const float d0 = g_dotv[2 * ntok], d1 = g_dotv[2 * ntok + 1];
                const int   p0 = g_idxv[2 * ntok], p1 = g_idxv[2 * ntok + 1];
#pragma unroll
                for (int nt = 0; nt < 4; nt++) {
                    const int o = n0 + warp_n * 32 + nt * 8 + qcol;
                    float v0 = acc[mt][nt][g * 2 + 0] + bo[nt][0]
                             + d0 * u[(size_t)o * POOLS + p0]
                             + d1 * u[(size_t)o * POOLS + p1];
                    float v1 = acc[mt][nt][g * 2 + 1] + bo[nt][1]
                             + d0 * u[(size_t)(o + 1) * POOLS + p0]
                             + d1 * u[(size_t)(o + 1) * POOLS + p1];
                    float2 v = make_float2(v0, v1);
                    *(float2*)(out + (size_t)ntok * OUT + o) = v;
                }
            }
    } else {
#pragma unroll
        for (int mt = 0; mt < 4; mt++)
#pragma unroll
            for (int g = 0; g < 2; g++) {
                const int ntok = m0 + warp_m * 64 + mt * 16 + g * 8 + qrow;
#pragma unroll
                for (int nt = 0; nt < 4; nt++) {
                    const int o = warp_n * 32 + nt * 8 + qcol;
                    float2 v = make_float2(acc[mt][nt][g * 2 + 0],
                                           acc[mt][nt][g * 2 + 1]);
                    *(float2*)(g_logits + (size_t)ntok * POOLS + o) = v;
                }
            }
    }
}

// ---------------------------------------------------------------------------
// Kernel 2: fp32 top-2 over logits + dot(x, svh[idx])  (exact fp32)
// Note: only the top-2 *set* matters (vals are unused; expert sum is
// order-symmetric), so selection is robust.
// ---------------------------------------------------------------------------
__global__ void __launch_bounds__(128)
topk_kernel(const float* __restrict__ x, const float* __restrict__ svh) {
    const int n = blockIdx.x;
    const int tid = threadIdx.x;
    __shared__ float lg[POOLS];
    __shared__ int sp[2];
    __shared__ float red[2][128];

    lg[tid] = g_logits[(size_t)n * POOLS + tid];
    __syncthreads();

    if (tid == 0) {
        float bv0 = lg[0]; int bi0 = 0;
        float bv1 = -3.402823466e38f; int bi1 = 0;
        for (int t = 1; t < POOLS; t++) {
            float v = lg[t];
            if (v > bv0)      { bv1 = bv0; bi1 = bi0; bv0 = v; bi0 = t; }
            else if (v > bv1) { bv1 = v;  bi1 = t; }
        }
        sp[0] = bi0; sp[1] = bi1;
    }
    __syncthreads();

    const int p0 = sp[0], p1 = sp[1];
    const float4* xr = (const float4*)(x   + (size_t)n  * IN);
    const float4* s0 = (const float4*)(svh + (size_t)p0 * IN);
    const float4* s1 = (const float4*)(svh + (size_t)p1 * IN);
    float a0 = 0.f, a1 = 0.f;
    for (int i = tid; i < IN / 4; i += 128) {
        float4 xv = xr[i], v0 = s0[i], v1 = s1[i];
        a0 += xv.x * v0.x + xv.y * v0.y + xv.z * v0.z + xv.w * v0.w;
        a1 += xv.x * v1.x + xv.y * v1.y + xv.z * v1.z + xv.w * v1.w;
    }
    red[0][tid] = a0; red[1][tid] = a1;
    __syncthreads();
    for (int s = 64; s > 0; s >>= 1) {
        if (tid < s) { red[0][tid] += red[0][tid + s]; red[1][tid] += red[1][tid + s]; }
        __syncthreads();
    }
    if (tid == 0) {
        g_dotv[2 * n]     = red[0][0];
        g_dotv[2 * n + 1] = red[1][0];
        g_idxv[2 * n]     = p0;
        g_idxv[2 * n + 1] = p1;
    }
}

// ---------------------------------------------------------------------------
// Launch
// ---------------------------------------------------------------------------
extern "C" void kernel_launch(void* const* d_in, const int* in_sizes, int n_in,
                              void* d_out, int out_size) {
    const float* x   = (const float*)d_in[0];
    const float* w0  = (const float*)d_in[1];
    const float* b0  = (const float*)d_in[2];
    const float* wr  = (const float*)d_in[3];
    const float* u   = (const float*)d_in[4];
    const float* svh = (const float*)d_in[5];
    float* out = (float*)d_out;

    static bool attr_done = false;
    if (!attr_done) {
        cudaFuncSetAttribute(gemm_kernel<true>,
                             cudaFuncAttributeMaxDynamicSharedMemorySize, SMEM_TOTAL);
        cudaFuncSetAttribute(gemm_kernel<false>,
                             cudaFuncAttributeMaxDynamicSharedMemorySize, SMEM_TOTAL);
        attr_done = true;
    }

    // 0) fp32 -> bf16 hi/lo split
    split_kernel<<<1024, 256>>>(x,  0, NTOK * IN);
    split_kernel<<<512,  256>>>(w0, 1, OUT * IN);
    split_kernel<<<64,   256>>>(wr, 2, POOLS * IN);

    // 1) router logits = x @ wr^T  (split-bf16, fp32-equivalent accuracy)
    gemm_kernel<false><<<NTOK / BM, THREADS, SMEM_TOTAL>>>(nullptr, nullptr, nullptr);

    // 2) exact fp32 top-2 + dot(x, svh[idx])
    topk_kernel<<<NTOK, 128>>>(x, svh);

    // 3) main GEMM + fused bias + rank-one epilogue
    gemm_kernel<true><<<(NTOK / BM) * (OUT / BN), THREADS, SMEM_TOTAL>>>(b0, u, out);
}

// round 6
// speedup vs baseline: 1.2314x; 1.2314x over previous
#include <cuda_runtime.h>
#include <cuda_bf16.h>
#include <cstdint>

#define DINLINE __device__ __forceinline__

// ---------------------------------------------------------------------------
// Problem constants
// ---------------------------------------------------------------------------
constexpr int NTOK  = 8192;   // B*S tokens
constexpr int IN    = 4096;
constexpr int OUT   = 4096;
constexpr int POOLS = 128;
constexpr int SEGS  = 3;      // bf16 split: xh*wh + xh*wl + xl*wh

constexpr int BK      = 64;   // bf16 per k-chunk -> 128B rows
constexpr int STAGES  = 4;
constexpr int THREADS = 256;  // 8 warps: 2 (m) x 4 (n)

constexpr int CHUNKS_PER_SEG = IN / BK;               // 64
constexpr int NC             = SEGS * CHUNKS_PER_SEG; // 192

// ---------------------------------------------------------------------------
// Device scratch (static __device__ globals only — no runtime allocation)
// ---------------------------------------------------------------------------
__device__ __align__(1024) __nv_bfloat16 g_xhi [(size_t)NTOK * IN];
__device__ __align__(1024) __nv_bfloat16 g_xlo [(size_t)NTOK * IN];
__device__ __align__(1024) __nv_bfloat16 g_whi [(size_t)OUT * IN];
__device__ __align__(1024) __nv_bfloat16 g_wlo [(size_t)OUT * IN];
__device__ __align__(1024) __nv_bfloat16 g_wrhi[(size_t)POOLS * IN];
__device__ __align__(1024) __nv_bfloat16 g_wrlo[(size_t)POOLS * IN];
__device__ __align__(1024) float g_logits[(size_t)NTOK * POOLS];
__device__ float g_dotv[(size_t)NTOK * 2];
__device__ int   g_idxv[(size_t)NTOK * 2];

// ---------------------------------------------------------------------------
// Portable PTX helpers (valid on plain sm_103 target — no tcgen05)
// ---------------------------------------------------------------------------
DINLINE uint32_t smem_u32(const void* p) {
    uint32_t a;
    asm("{ .reg .u64 t; cvta.to.shared.u64 t, %1; cvt.u32.u64 %0, t; }" : "=r"(a) : "l"(p));
    return a;
}

// 128B-row swizzle: 16B-chunk index (bits 4..6) ^= low 3 bits of row (bits 7..9)
#define SWZ128(o) ((o) ^ (((o) >> 3) & 0x70))

#define CP_ASYNC16(saddr, gptr) \
    asm volatile("cp.async.cg.shared.global [%0], [%1], 16;" :: "r"(saddr), "l"(gptr))
#define CP_COMMIT() asm volatile("cp.async.commit_group;" ::: "memory")
#define CP_WAIT2()  asm volatile("cp.async.wait_group 2;"  ::: "memory")

DINLINE void ldsm_x4(uint32_t* r, uint32_t addr) {
    asm volatile("ldmatrix.sync.aligned.m8n8.x4.shared.b16 {%0,%1,%2,%3}, [%4];"
                 : "=r"(r[0]), "=r"(r[1]), "=r"(r[2]), "=r"(r[3]) : "r"(addr));
}

DINLINE void mma16816(float* d, const uint32_t* a, uint32_t b0, uint32_t b1) {
    asm volatile(
        "mma.sync.aligned.m16n8k16.row.col.f32.bf16.bf16.f32 "
        "{%0,%1,%2,%3}, {%4,%5,%6,%7}, {%8,%9}, {%0,%1,%2,%3};"
        : "+f"(d[0]), "+f"(d[1]), "+f"(d[2]), "+f"(d[3])
        : "r"(a[0]), "r"(a[1]), "r"(a[2]), "r"(a[3]), "r"(b0), "r"(b1));
}

// ---------------------------------------------------------------------------
// Kernel 0: fp32 -> (bf16 hi, bf16 lo) split (vectorized)
// ---------------------------------------------------------------------------
__global__ void split_kernel(const float* __restrict__ src, int which, int n2) {
    __nv_bfloat16* hi = (which == 0) ? g_xhi : (which == 1) ? g_whi : g_wrhi;
    __nv_bfloat16* lo = (which == 0) ? g_xlo : (which == 1) ? g_wlo : g_wrlo;
    int i = blockIdx.x * blockDim.x + threadIdx.x;
    int stride = gridDim.x * blockDim.x;
    const float2* s2 = (const float2*)src;
    __nv_bfloat162* h2 = (__nv_bfloat162*)hi;
    __nv_bfloat162* l2 = (__nv_bfloat162*)lo;
    for (; i < n2; i += stride) {
        float2 v = s2[i];
        __nv_bfloat16 ha = __float2bfloat16(v.x);
        __nv_bfloat16 hb = __float2bfloat16(v.y);
        __nv_bfloat162 h; h.x = ha; h.y = hb;
        __nv_bfloat162 l;
        l.x = __float2bfloat16(v.x - __bfloat162float(ha));
        l.y = __float2bfloat16(v.y - __bfloat162float(hb));
        h2[i] = h;
        l2[i] = l;
    }
}

// ---------------------------------------------------------------------------
// GEMM: out = x @ W^T with split-bf16 (fp32-equivalent accuracy).
//   MAIN=false: logits[8192,128] = x @ wr^T         (BM=64,  BN=128)
//   MAIN=true : out[8192,4096]  = x @ w0^T + b0 + rank-one epilogue
//                                                    (BM=128, BN=256)
// cp.async 4-stage pipeline (single barrier per chunk), ldmatrix + mma.sync.
// 8 warps = 2(m) x 4(n); warp tile (BM/2) x (BN/4).
// ---------------------------------------------------------------------------
template <int TBM, int TBN, bool MAIN>
__global__ void __launch_bounds__(THREADS, 1)
gemm_kernel(const float* __restrict__ b0v, const float* __restrict__ u,
            float* __restrict__ out) {
    constexpr int WM  = TBM / 2;          // warp tile m
    constexpr int WN  = TBN / 4;          // warp tile n
    constexpr int MT  = WM / 16;          // A 16x16 tiles per warp
    constexpr int NT2 = WN / 16;          // B 16x16 ldsm tiles per warp
    constexpr int NT8 = WN / 8;           // mma n-strips per warp
    constexpr int A_B = TBM * 128;
    constexpr int B_B = TBN * 128;
    constexpr int STG = A_B + B_B;

    extern __shared__ __align__(1024) char smem[];
    const uint32_t smem_base = smem_u32(smem);

    const int tid    = threadIdx.x;
    const int wid    = tid >> 5;
    const int lane   = tid & 31;
    const int warp_m = wid & 1;
    const int warp_n = wid >> 1;

    // group-swizzled CTA rasterization (L2 reuse)
    constexpr int GM = 16;
    const int num_n = MAIN ? (OUT / TBN) : 1;
    const int per_group = GM * num_n;
    const int id = blockIdx.x;
    const int m_tile = (id / per_group) * GM + (id % per_group) % GM;
    const int n_tile = (id % per_group) / GM;
    const int m0 = m_tile * TBM;
    const int n0 = n_tile * TBN;

    const __nv_bfloat16* Aseg[SEGS] = {g_xhi, g_xhi, g_xlo};
    const __nv_bfloat16* Bseg[SEGS];
    if (MAIN) { Bseg[0] = g_whi;  Bseg[1] = g_wlo;  Bseg[2] = g_whi;  }
    else      { Bseg[0] = g_wrhi; Bseg[1] = g_wrlo; Bseg[2] = g_wrhi; }

    auto load_chunk = [&](int chunk, int stage) {
        const int seg = chunk >> 6;          // / CHUNKS_PER_SEG
        const int kc  = chunk & 63;
        const __nv_bfloat16* Ap = Aseg[seg] + (size_t)m0 * IN + kc * BK;
        const __nv_bfloat16* Bp = Bseg[seg] + (size_t)n0 * IN + kc * BK;
        const uint32_t sA = smem_base + stage * STG;
        const uint32_t sB = sA + A_B;
#pragma unroll
        for (int it = 0; it < TBM / 32; it++) {   // TBM rows x 8 chunks of 16B
            int s = tid + it * THREADS;
            int row = s >> 3, c = s & 7;
            CP_ASYNC16(sA + SWZ128((uint32_t)(row * 128 + c * 16)),
                       (const void*)(Ap + (size_t)row * IN + c * 8));
        }
#pragma unroll
        for (int it = 0; it < TBN / 32; it++) {
            int s = tid + it * THREADS;
            int row = s >> 3, c = s & 7;
            CP_ASYNC16(sB + SWZ128((uint32_t)(row * 128 + c * 16)),
                       (const void*)(Bp + (size_t)row * IN + c * 8));
        }
    };

    // ldmatrix per-thread addressing
    const int xorv = lane & 7;
    const int a_hi = lane >> 4;
    const int b_hi = (lane >> 3) & 1;
    uint32_t a_row[MT], b_row[NT2];
#pragma unroll
    for (int mt = 0; mt < MT; mt++)
        a_row[mt] = (uint32_t)((warp_m * WM + mt * 16 + (lane & 15)) * 128);
#pragma unroll
    for (int nt2 = 0; nt2 < NT2; nt2++)
        b_row[nt2] = (uint32_t)(A_B +
                     (warp_n * WN + nt2 * 16 + ((lane & 7) | ((lane & 16) >> 1))) * 128);

    float acc[MT][NT8][4] = {};

    // prologue: stages 0..STAGES-2
#pragma unroll
    for (int s = 0; s < STAGES - 1; s++) { load_chunk(s, s); CP_COMMIT(); }

    for (int i = 0; i < NC; i++) {
        CP_WAIT2();              // chunk i resident (own-thread copies)
        __syncthreads();         // visibility + all warps done with chunk i-1

        const uint32_t sbase = smem_base + (i & (STAGES - 1)) * STG;
#pragma unroll
        for (int ks = 0; ks < 4; ks++) {
            uint32_t af[MT][4], bf[NT2][4];
            const uint32_t achunk = (uint32_t)((ks * 2 + a_hi) ^ xorv) << 4;
            const uint32_t bchunk = (uint32_t)((ks * 2 + b_hi) ^ xorv) << 4;
#pragma unroll
            for (int mt = 0; mt < MT; mt++)
                ldsm_x4(af[mt], sbase + a_row[mt] + achunk);
#pragma unroll
            for (int nt2 = 0; nt2 < NT2; nt2++)
                ldsm_x4(bf[nt2], sbase + b_row[nt2] + bchunk);
#pragma unroll
            for (int mt = 0; mt < MT; mt++)
#pragma unroll
                for (int nt2 = 0; nt2 < NT2; nt2++) {
                    mma16816(acc[mt][nt2 * 2 + 0], af[mt], bf[nt2][0], bf[nt2][1]);
                    mma16816(acc[mt][nt2 * 2 + 1], af[mt], bf[nt2][2], bf[nt2][3]);
                }
        }

        // prefetch next chunk into the stage all warps just finished with
        const int nxt = i + STAGES - 1;
        if (nxt < NC) load_chunk(nxt, nxt & (STAGES - 1));
        CP_COMMIT();
    }

    // ---------------- epilogue (C frag: rows qrow,+8; cols qcol,+1) ---------
    const int qrow = lane >> 2;
    const int qcol = (lane & 3) * 2;

    if (MAIN) {
        // stage u[n0 .. n0+TBN) x POOLS into smem (padded stride 132 words)
        __syncthreads();         // mainloop smem reads fully drained
        float* us = (float*)smem;
        constexpr int USTR = 132;
#pragma unroll 4
        for (int idx = tid; idx < TBN * (POOLS / 4); idx += THREADS) {
            int o  = idx >> 5;           // 32 float4 per row
            int p4 = idx & 31;
            float4 v = *(const float4*)(u + (size_t)(n0 + o) * POOLS + p4 * 4);
            *(float4*)(us + o * USTR + p4 * 4) = v;
        }
        __syncthreads();

        float bo[NT8][2];
#pragma unroll
        for (int nt = 0; nt < NT8; nt++) {
            int o = n0 + warp_n * WN + nt * 8 + qcol;
            bo[nt][0] = b0v[o];
            bo[nt][1] = b0v[o + 1];
        }
#pragma unroll
        for (int mt = 0; mt < MT; mt++)
#pragma unroll
            for (int g = 0; g < 2; g++) {
                const int ntok = m0 + warp_m * WM + mt * 16 + g * 8 + qrow;
                const float d0 = g_dotv[2 * ntok], d1 = g_dotv[2 * ntok + 1];
                const int   p0 = g_idxv[2 * ntok], p1 = g_idxv[2 * ntok + 1];
#pragma unroll
                for (int nt = 0; nt < NT8; nt++) {
                    const int ol = warp_n * WN + nt * 8 + qcol;
                    float v0 = acc[mt][nt][g * 2 + 0] + bo[nt][0]
                             + d0 * us[ol * USTR + p0]
                             + d1 * us[ol * USTR + p1];
                    float v1 = acc[mt][nt][g * 2 + 1] + bo[nt][1]
                             + d0 * us[(ol + 1) * USTR + p0]
                             + d1 * us[(ol + 1) * USTR + p1];
                    *(float2*)(out + (size_t)ntok * OUT + n0 + ol) = make_float2(v0, v1);
                }
            }
    } else {
#pragma unroll
        for (int mt = 0; mt < MT; mt++)
#pragma unroll
            for (int g = 0; g < 2; g++) {
                const int ntok = m0 + warp_m * WM + mt * 16 + g * 8 + qrow;
#pragma unroll
                for (int nt = 0; nt < NT8; nt++) {
                    const int o = warp_n * WN + nt * 8 + qcol;
                    *(float2*)(g_logits + (size_t)ntok * POOLS + o) =
                        make_float2(acc[mt][nt][g * 2 + 0], acc[mt][nt][g * 2 + 1]);
                }
            }
    }
}

// ---------------------------------------------------------------------------
// Kernel 2: fp32 top-2 over logits + dot(x, svh[idx])  (exact fp32)
// (only the top-2 *set* matters: vals are unused; expert sum is symmetric)
// ---------------------------------------------------------------------------
__global__ void __launch_bounds__(128)
topk_kernel(const float* __restrict__ x, const float* __restrict__ svh) {
    const int n = blockIdx.x;
    const int tid = threadIdx.x;
    __shared__ float lg[POOLS];
    __shared__ int sp[2];
    __shared__ float red[2][128];

    lg[tid] = g_logits[(size_t)n * POOLS + tid];
    __syncthreads();

    if (tid == 0) {
        float bv0 = lg[0]; int bi0 = 0;
        float bv1 = -3.402823466e38f; int bi1 = 0;
        for (int t = 1; t < POOLS; t++) {
            float v = lg[t];
            if (v > bv0)      { bv1 = bv0; bi1 = bi0; bv0 = v; bi0 = t; }
            else if (v > bv1) { bv1 = v;  bi1 = t; }
        }
        sp[0] = bi0; sp[1] = bi1;
    }
    __syncthreads();

    const int p0 = sp[0], p1 = sp[1];
    const float4* xr = (const float4*)(x   + (size_t)n  * IN);
    const float4* s0 = (const float4*)(svh + (size_t)p0 * IN);
    const float4* s1 = (const float4*)(svh + (size_t)p1 * IN);
    float a0 = 0.f, a1 = 0.f;
    for (int i = tid; i < IN / 4; i += 128) {
        float4 xv = xr[i], v0 = s0[i], v1 = s1[i];
        a0 += xv.x * v0.x + xv.y * v0.y + xv.z * v0.z + xv.w * v0.w;
        a1 += xv.x * v1.x + xv.y * v1.y + xv.z * v1.z + xv.w * v1.w;
    }
    red[0][tid] = a0; red[1][tid] = a1;
    __syncthreads();
    for (int s = 64; s > 0; s >>= 1) {
        if (tid < s) { red[0][tid] += red[0][tid + s]; red[1][tid] += red[1][tid + s]; }
        __syncthreads();
    }
    if (tid == 0) {
        g_dotv[2 * n]     = red[0][0];
        g_dotv[2 * n + 1] = red[1][0];
        g_idxv[2 * n]     = p0;
        g_idxv[2 * n + 1] = p1;
    }
}

// ---------------------------------------------------------------------------
// Launch
// ---------------------------------------------------------------------------
extern "C" void kernel_launch(void* const* d_in, const int* in_sizes, int n_in,
                              void* d_out, int out_size) {
    const float* x   = (const float*)d_in[0];
    const float* w0  = (const float*)d_in[1];
    const float* b0  = (const float*)d_in[2];
    const float* wr  = (const float*)d_in[3];
    const float* u   = (const float*)d_in[4];
    const float* svh = (const float*)d_in[5];
    float* out = (float*)d_out;

    constexpr int SMEM_MAIN = STAGES * (128 + 256) * 128;   // 196,608 B
    constexpr int SMEM_RTR  = STAGES * (64 + 128) * 128;    //  98,304 B

    static bool attr_done = false;
    if (!attr_done) {
        cudaFuncSetAttribute(gemm_kernel<128, 256, true>,
                             cudaFuncAttributeMaxDynamicSharedMemorySize, SMEM_MAIN);
        cudaFuncSetAttribute(gemm_kernel<64, 128, false>,
                             cudaFuncAttributeMaxDynamicSharedMemorySize, SMEM_RTR);
        attr_done = true;
    }

    // 0) fp32 -> bf16 hi/lo split (vectorized, float2 granularity)
    split_kernel<<<1024, 256>>>(x,  0, NTOK * IN / 2);
    split_kernel<<<512,  256>>>(w0, 1, OUT * IN / 2);
    split_kernel<<<64,   256>>>(wr, 2, POOLS * IN / 2);

    // 1) router logits = x @ wr^T  (BM=64 -> 128 CTAs, 86% SM coverage)
    gemm_kernel<64, 128, false><<<NTOK / 64, THREADS, SMEM_RTR>>>(nullptr, nullptr, nullptr);

    // 2) exact fp32 top-2 + dot(x, svh[idx])
    topk_kernel<<<NTOK, 128>>>(x, svh);

    // 3) main GEMM + fused bias + rank-one epilogue (BM=128, BN=256)
    gemm_kernel<128, 256, true><<<(NTOK / 128) * (OUT / 256), THREADS, SMEM_MAIN>>>(b0, u, out);
}